// round 2
// baseline (speedup 1.0000x reference)
#include <cuda_runtime.h>
#include <cuda_bf16.h>
#include <math.h>
#include <stdint.h>

// Problem constants
#define Bsz 4
#define Tn 2048
#define Cn 2048
#define Hn 16
#define DKn 64
#define DVn 128
#define Mtok (Bsz*Tn)          // 8192
#define KEYD (Hn*DKn)          // 1024
#define VALD (Hn*DVn)          // 2048

// -------------------- scratch (device globals, no allocation) --------------------
__device__ float g_qk[(size_t)Mtok*2048];   // x @ qk_w^T
__device__ float g_vg[(size_t)Mtok*4096];   // x @ vg_w^T
__device__ float g_q [(size_t)Mtok*KEYD];   // conv+silu+l2norm q
__device__ float g_k [(size_t)Mtok*KEYD];
__device__ float g_v [(size_t)Mtok*VALD];
__device__ float g_dc[(size_t)Mtok*Hn];     // exp(g) decay
__device__ float g_bt[(size_t)Mtok*Hn];     // beta
__device__ float g_op[(size_t)Mtok*VALD];   // scan output (pre-norm)
__device__ float g_ob[(size_t)Mtok*VALD];   // gated/normalized output

// -------------------- cp.async helpers --------------------
__device__ __forceinline__ void cp16(void* s, const void* g) {
    unsigned ss = (unsigned)__cvta_generic_to_shared(s);
    asm volatile("cp.async.cg.shared.global [%0], [%1], 16;\n" :: "r"(ss), "l"(g));
}
__device__ __forceinline__ void cp4(void* s, const void* g) {
    unsigned ss = (unsigned)__cvta_generic_to_shared(s);
    asm volatile("cp.async.ca.shared.global [%0], [%1], 4;\n" :: "r"(ss), "l"(g));
}
#define CP_COMMIT asm volatile("cp.async.commit_group;\n" ::: "memory")
#define CP_WAIT1  asm volatile("cp.async.wait_group 1;\n" ::: "memory")

__device__ __forceinline__ unsigned tf32cvt(float f) {
    unsigned u;
    asm("cvt.rna.tf32.f32 %0, %1;" : "=r"(u) : "f"(f));
    return u;
}
// split f into hi (tf32) + lo (tf32 of residual)
__device__ __forceinline__ void tf32split(float f, unsigned& hi, unsigned& lo) {
    hi = tf32cvt(f);
    float r = f - __uint_as_float(hi);
    lo = tf32cvt(r);
}
__device__ __forceinline__ void mma8(float* c, const unsigned* a, const unsigned* b) {
    asm volatile(
        "mma.sync.aligned.m16n8k8.row.col.f32.tf32.tf32.f32 "
        "{%0,%1,%2,%3},{%4,%5,%6,%7},{%8,%9},{%0,%1,%2,%3};\n"
        : "+f"(c[0]), "+f"(c[1]), "+f"(c[2]), "+f"(c[3])
        : "r"(a[0]), "r"(a[1]), "r"(a[2]), "r"(a[3]), "r"(b[0]), "r"(b[1]));
}

// ==================== 3xTF32 GEMM: C[M,N] = A[M,K] @ B[N,K]^T ====================
// Split-precision: C += Ah*Bh + Ah*Bl + Al*Bh  (error ~2^-22, effectively fp32)
// Requires M%128==0, N%128==0, K%16==0 (true for all calls here).
#define GBM 128
#define GBN 128
#define GBK 16
#define GST 20   // BK + pad

__global__ __launch_bounds__(256) void gemm_tf32x3(
    const float* __restrict__ A, const float* __restrict__ Bw,
    float* __restrict__ C, int M, int N, int K)
{
    __shared__ __align__(16) float As[2][GBM][GST];
    __shared__ __align__(16) float Bs[2][GBN][GST];

    const int bm = blockIdx.y * GBM, bn = blockIdx.x * GBN;
    const int tid = threadIdx.x, lane = tid & 31, wid = tid >> 5;
    const int wm = (wid >> 2) * 64, wn = (wid & 3) * 32;
    const int g4 = lane >> 2, t4 = lane & 3;

    float acc[4][4][4];
#pragma unroll
    for (int i = 0; i < 4; i++)
#pragma unroll
        for (int j = 0; j < 4; j++)
#pragma unroll
            for (int r = 0; r < 4; r++) acc[i][j][r] = 0.f;

    const int nk = K / GBK;

#define LOADSTAGE(s, k0) {                                                        \
        _Pragma("unroll")                                                         \
        for (int rr = 0; rr < 2; rr++) {                                          \
            int idx = tid + rr * 256;                                             \
            int row = idx >> 2, qq = (idx & 3) * 4;                               \
            cp16(&As[s][row][qq], A  + (size_t)(bm + row) * K + (k0) + qq);       \
            cp16(&Bs[s][row][qq], Bw + (size_t)(bn + row) * K + (k0) + qq);       \
        }                                                                         \
    }

    LOADSTAGE(0, 0);
    CP_COMMIT;

    for (int kt = 0; kt < nk; kt++) {
        const int s = kt & 1;
        if (kt + 1 < nk) LOADSTAGE(s ^ 1, (kt + 1) * GBK);
        CP_COMMIT;
        CP_WAIT1;
        __syncthreads();

#pragma unroll
        for (int ks = 0; ks < 2; ks++) {
            const int kk = ks * 8;
            unsigned ah[4][4], al[4][4], bh[4][2], bl[4][2];
#pragma unroll
            for (int mf = 0; mf < 4; mf++) {
                int r0 = wm + mf * 16 + g4;
                tf32split(As[s][r0    ][kk + t4    ], ah[mf][0], al[mf][0]);
                tf32split(As[s][r0 + 8][kk + t4    ], ah[mf][1], al[mf][1]);
                tf32split(As[s][r0    ][kk + t4 + 4], ah[mf][2], al[mf][2]);
                tf32split(As[s][r0 + 8][kk + t4 + 4], ah[mf][3], al[mf][3]);
            }
#pragma unroll
            for (int nf = 0; nf < 4; nf++) {
                int c0 = wn + nf * 8 + g4;
                tf32split(Bs[s][c0][kk + t4    ], bh[nf][0], bl[nf][0]);
                tf32split(Bs[s][c0][kk + t4 + 4], bh[nf][1], bl[nf][1]);
            }
#pragma unroll
            for (int mf = 0; mf < 4; mf++)
#pragma unroll
                for (int nf = 0; nf < 4; nf++) {
                    mma8(acc[mf][nf], al[mf], bh[nf]);   // lo*hi
                    mma8(acc[mf][nf], ah[mf], bl[nf]);   // hi*lo
                    mma8(acc[mf][nf], ah[mf], bh[nf]);   // hi*hi (last: largest term)
                }
        }
        __syncthreads();
    }

    // epilogue
#pragma unroll
    for (int mf = 0; mf < 4; mf++) {
#pragma unroll
        for (int nf = 0; nf < 4; nf++) {
            int row = bm + wm + mf * 16 + g4;
            int col = bn + wn + nf * 8 + 2 * t4;
            float2 v0 = make_float2(acc[mf][nf][0], acc[mf][nf][1]);
            float2 v1 = make_float2(acc[mf][nf][2], acc[mf][nf][3]);
            *(float2*)(C + (size_t)row * N + col)       = v0;
            *(float2*)(C + (size_t)(row + 8) * N + col) = v1;
        }
    }
#undef LOADSTAGE
}

// ==================== beta / decay projections ====================
__global__ __launch_bounds__(256) void proj_gb(
    const float* __restrict__ x,
    const float* __restrict__ aw, const float* __restrict__ bw,
    const float* __restrict__ bbias, const float* __restrict__ betab,
    const float* __restrict__ alog, const float* __restrict__ dtb,
    float* __restrict__ decout, float* __restrict__ betaout)
{
    const int m = blockIdx.x;
    const int tid = threadIdx.x, lane = tid & 31, wid = tid >> 5;
    __shared__ float raw[32];
    const float* xr = x + (size_t)m * Cn;
#pragma unroll
    for (int i = 0; i < 4; i++) {
        int idx = wid * 4 + i;
        const float* wr = (idx < 16) ? (aw + (size_t)idx * Cn)
                                     : (bw + (size_t)(idx - 16) * Cn);
        float accv = 0.f;
        for (int k2 = lane; k2 < Cn; k2 += 32) accv += xr[k2] * wr[k2];
#pragma unroll
        for (int o = 16; o; o >>= 1) accv += __shfl_xor_sync(0xffffffffu, accv, o);
        if (lane == 0) raw[idx] = accv;
    }
    __syncthreads();
    if (tid < 16) {
        int h = tid;
        float sa = raw[h] + dtb[h];
        float sp = (sa > 20.f) ? sa : log1pf(expf(sa));
        float g  = -expf(alog[h]) * sp;
        decout[(size_t)m * Hn + h] = expf(g);           // precomputed decay
        float sb = raw[16 + h] + bbias[h] + betab[h];
        betaout[(size_t)m * Hn + h] = 2.f / (1.f + expf(-sb));
    }
}

// ==================== causal depthwise conv(4) + silu ====================
__global__ void conv_silu(
    const float* __restrict__ in, int ldin, int off,
    const float* __restrict__ w, float* __restrict__ out,
    int CH, int total)
{
    int idx = blockIdx.x * blockDim.x + threadIdx.x;
    if (idx >= total) return;
    int c = idx % CH;
    int t = (idx / CH) % Tn;
    int b = idx / (CH * Tn);
    const float* w4 = w + (size_t)c * 4;
    size_t base = ((size_t)b * Tn) * ldin + off + c;
    float accv = 0.f;
#pragma unroll
    for (int j = 0; j < 4; j++) {
        int tt = t + j - 3;
        if (tt >= 0) accv += w4[j] * in[base + (size_t)tt * ldin];
    }
    out[idx] = accv / (1.f + expf(-accv));
}

// ==================== l2 norm over DK=64 groups (optionally * SCALE) ====================
__global__ __launch_bounds__(256) void l2norm_scale(
    float* __restrict__ p, int ngroups, float scale)
{
    int grp = blockIdx.x * 8 + (threadIdx.x >> 5);
    if (grp >= ngroups) return;
    int lane = threadIdx.x & 31;
    float* ptr = p + (size_t)grp * 64;
    float a = ptr[lane], b2 = ptr[lane + 32];
    float ss = a * a + b2 * b2;
#pragma unroll
    for (int o = 16; o; o >>= 1) ss += __shfl_xor_sync(0xffffffffu, ss, o);
    float r = rsqrtf(ss + 1e-6f) * scale;
    ptr[lane] = a * r;
    ptr[lane + 32] = b2 * r;
}

// ==================== gated delta rule recurrent scan ====================
// grid = B*H*SPLIT blocks, 128 threads. Block owns (b, h, 64 of the 128 DV cols).
// Thread (jl = tid>>1, kh = tid&1) owns state S[k = kh*32 .. kh*32+31][col jl].
#define SPLIT 2
#define CHK 16
__global__ __launch_bounds__(128) void scan_kernel(
    const float* __restrict__ qn, const float* __restrict__ kn,
    const float* __restrict__ vv, const float* __restrict__ dec,
    const float* __restrict__ bet, float* __restrict__ op)
{
    __shared__ __align__(16) float qs[2][CHK][64];
    __shared__ __align__(16) float ks[2][CHK][64];
    __shared__ __align__(16) float vs[2][CHK][64];
    __shared__ float gs[2][CHK], bs[2][CHK];

    const int bid = blockIdx.x;
    const int vh = bid & (SPLIT - 1);
    const int h  = (bid / SPLIT) & (Hn - 1);
    const int b  = bid / (SPLIT * Hn);
    const int tid = threadIdx.x;
    const int jl = tid >> 1, kh = tid & 1;

    float S[32];
#pragma unroll
    for (int i = 0; i < 32; i++) S[i] = 0.f;

#define LOADCHUNK(s, t0) {                                                          \
        _Pragma("unroll")                                                           \
        for (int rr = 0; rr < 2; rr++) {                                            \
            int idx = tid + rr * 128;                                               \
            int row = idx >> 4, q4i = (idx & 15) * 4;                               \
            size_t tb = (size_t)(b * Tn + (t0) + row);                              \
            cp16(&qs[s][row][q4i], qn + (tb * Hn + h) * 64 + q4i);                  \
            cp16(&ks[s][row][q4i], kn + (tb * Hn + h) * 64 + q4i);                  \
            cp16(&vs[s][row][q4i], vv + tb * VALD + h * DVn + vh * 64 + q4i);       \
        }                                                                           \
        if (tid < CHK)            cp4(&gs[s][tid],      dec + (size_t)(b*Tn+(t0)+tid)*Hn + h);        \
        else if (tid < 2*CHK)     cp4(&bs[s][tid-CHK],  bet + (size_t)(b*Tn+(t0)+tid-CHK)*Hn + h);    \
    }

    LOADCHUNK(0, 0);
    CP_COMMIT;

    const int NC = Tn / CHK;
    for (int c = 0; c < NC; c++) {
        const int s = c & 1;
        if (c + 1 < NC) LOADCHUNK(s ^ 1, (c + 1) * CHK);
        CP_COMMIT;
        CP_WAIT1;
        __syncthreads();

        const int t0 = c * CHK;
#pragma unroll 1
        for (int r = 0; r < CHK; r++) {
            const float ge  = gs[s][r];
            const float btc = bs[s][r];
            const float vj  = vs[s][r][jl];
            const float4* kp = (const float4*)&ks[s][r][kh * 32];
            const float4* qp = (const float4*)&qs[s][r][kh * 32];

            float kreg[32];
            float m0 = 0.f, m1 = 0.f, m2 = 0.f, m3 = 0.f;
#pragma unroll
            for (int i = 0; i < 8; i++) {
                float4 k4 = kp[i];
                float s0 = S[4*i+0] * ge, s1 = S[4*i+1] * ge;
                float s2 = S[4*i+2] * ge, s3 = S[4*i+3] * ge;
                m0 += k4.x * s0; m1 += k4.y * s1; m2 += k4.z * s2; m3 += k4.w * s3;
                S[4*i+0] = s0; S[4*i+1] = s1; S[4*i+2] = s2; S[4*i+3] = s3;
                kreg[4*i+0] = k4.x; kreg[4*i+1] = k4.y;
                kreg[4*i+2] = k4.z; kreg[4*i+3] = k4.w;
            }
            float mem = (m0 + m1) + (m2 + m3);
            mem += __shfl_xor_sync(0xffffffffu, mem, 1);
            const float delta = (vj - mem) * btc;

            float o0 = 0.f, o1 = 0.f, o2 = 0.f, o3 = 0.f;
#pragma unroll
            for (int i = 0; i < 8; i++) {
                float4 q4 = qp[i];
                float s0 = S[4*i+0] + kreg[4*i+0] * delta;
                float s1 = S[4*i+1] + kreg[4*i+1] * delta;
                float s2 = S[4*i+2] + kreg[4*i+2] * delta;
                float s3 = S[4*i+3] + kreg[4*i+3] * delta;
                o0 += q4.x * s0; o1 += q4.y * s1; o2 += q4.z * s2; o3 += q4.w * s3;
                S[4*i+0] = s0; S[4*i+1] = s1; S[4*i+2] = s2; S[4*i+3] = s3;
            }
            float ov = (o0 + o1) + (o2 + o3);
            ov += __shfl_xor_sync(0xffffffffu, ov, 1);
            if (kh == 0)
                op[(((size_t)(b * Tn + t0 + r)) * Hn + h) * DVn + vh * 64 + jl] = ov;
        }
        __syncthreads();
    }
#undef LOADCHUNK
}

// ==================== RMS over DV + silu(g_out) gate ====================
__global__ __launch_bounds__(256) void rms_gate(
    const float* __restrict__ op, const float* __restrict__ vg,
    float* __restrict__ ob)
{
    int grp = blockIdx.x * 8 + (threadIdx.x >> 5);   // grp = m*16 + h
    int lane = threadIdx.x & 31;
    const float4* src = (const float4*)(op + (size_t)grp * 128);
    float4 o4 = src[lane];
    float ss = o4.x * o4.x + o4.y * o4.y + o4.z * o4.z + o4.w * o4.w;
#pragma unroll
    for (int o = 16; o; o >>= 1) ss += __shfl_xor_sync(0xffffffffu, ss, o);
    float r = rsqrtf(ss * (1.f / 128.f) + 1.1920929e-7f);
    int m = grp >> 4, h = grp & 15;
    const float4* gp = (const float4*)(vg + (size_t)m * 4096 + 2048 + h * 128);
    float4 gg = gp[lane];
    float4 res;
    res.x = o4.x * r * (gg.x / (1.f + expf(-gg.x)));
    res.y = o4.y * r * (gg.y / (1.f + expf(-gg.y)));
    res.z = o4.z * r * (gg.z / (1.f + expf(-gg.z)));
    res.w = o4.w * r * (gg.w / (1.f + expf(-gg.w)));
    ((float4*)(ob + (size_t)m * 2048 + h * 128))[lane] = res;
}

// ==================== launch ====================
extern "C" void kernel_launch(void* const* d_in, const int* in_sizes, int n_in,
                              void* d_out, int out_size)
{
    const float* x      = (const float*)d_in[0];
    const float* qk_w   = (const float*)d_in[1];
    const float* vg_w   = (const float*)d_in[2];
    const float* o_w    = (const float*)d_in[3];
    const float* a_w    = (const float*)d_in[4];
    const float* b_w    = (const float*)d_in[5];
    const float* b_bias = (const float*)d_in[6];
    const float* beta_b = (const float*)d_in[7];
    const float* A_log  = (const float*)d_in[8];
    const float* dt_b   = (const float*)d_in[9];
    const float* q_cw   = (const float*)d_in[10];
    const float* k_cw   = (const float*)d_in[11];
    const float* v_cw   = (const float*)d_in[12];
    float* out = (float*)d_out;

    float *qk, *vg, *q, *k, *v, *dc, *bt, *op, *ob;
    cudaGetSymbolAddress((void**)&qk, g_qk);
    cudaGetSymbolAddress((void**)&vg, g_vg);
    cudaGetSymbolAddress((void**)&q,  g_q);
    cudaGetSymbolAddress((void**)&k,  g_k);
    cudaGetSymbolAddress((void**)&v,  g_v);
    cudaGetSymbolAddress((void**)&dc, g_dc);
    cudaGetSymbolAddress((void**)&bt, g_bt);
    cudaGetSymbolAddress((void**)&op, g_op);
    cudaGetSymbolAddress((void**)&ob, g_ob);

    // 1) big projections (3xTF32 split precision)
    gemm_tf32x3<<<dim3(2048 / GBN, Mtok / GBM), 256>>>(x, qk_w, qk, Mtok, 2048, Cn);
    gemm_tf32x3<<<dim3(4096 / GBN, Mtok / GBM), 256>>>(x, vg_w, vg, Mtok, 4096, Cn);

    // 2) beta + decay
    proj_gb<<<Mtok, 256>>>(x, a_w, b_w, b_bias, beta_b, A_log, dt_b, dc, bt);

    // 3) depthwise conv + silu
    {
        int tq = Mtok * KEYD;
        conv_silu<<<(tq + 255) / 256, 256>>>(qk, 2048, 0,    q_cw, q, KEYD, tq);
        conv_silu<<<(tq + 255) / 256, 256>>>(qk, 2048, KEYD, k_cw, k, KEYD, tq);
        int tv = Mtok * VALD;
        conv_silu<<<(tv + 255) / 256, 256>>>(vg, 4096, 0,    v_cw, v, VALD, tv);
    }

    // 4) l2 norm (q also gets SCALE = DK^-0.5 = 0.125)
    l2norm_scale<<<Mtok * Hn / 8, 256>>>(q, Mtok * Hn, 0.125f);
    l2norm_scale<<<Mtok * Hn / 8, 256>>>(k, Mtok * Hn, 1.0f);

    // 5) recurrent scan
    scan_kernel<<<Bsz * Hn * SPLIT, 128>>>(q, k, v, dc, bt, op);

    // 6) RMS + gate
    rms_gate<<<Mtok * Hn / 8, 256>>>(op, vg, ob);

    // 7) output projection (3xTF32)
    gemm_tf32x3<<<dim3(2048 / GBN, Mtok / GBM), 256>>>(ob, o_w, out, Mtok, 2048, Cn);
}

// round 4
// speedup vs baseline: 1.6128x; 1.6128x over previous
#include <cuda_runtime.h>
#include <cuda_bf16.h>
#include <math.h>
#include <stdint.h>

// Problem constants
#define Bsz 4
#define Tn 2048
#define Cn 2048
#define Hn 16
#define DKn 64
#define DVn 128
#define Mtok (Bsz*Tn)          // 8192
#define KEYD (Hn*DKn)          // 1024
#define VALD (Hn*DVn)          // 2048

// -------------------- scratch (device globals, no allocation) --------------------
__device__ float g_qk[(size_t)Mtok*2048];   // x @ qk_w^T
__device__ float g_vg[(size_t)Mtok*4096];   // x @ vg_w^T
__device__ float g_q [(size_t)Mtok*KEYD];
__device__ float g_k [(size_t)Mtok*KEYD];
__device__ float g_v [(size_t)Mtok*VALD];
__device__ float g_dc[(size_t)Mtok*Hn];
__device__ float g_bt[(size_t)Mtok*Hn];
__device__ float g_op[(size_t)Mtok*VALD];
__device__ float g_ob[(size_t)Mtok*VALD];

// bf16 hi/lo split operands for the tensor GEMMs
__device__ __nv_bfloat16 g_xh [(size_t)Mtok*Cn],  g_xl [(size_t)Mtok*Cn];
__device__ __nv_bfloat16 g_qwh[(size_t)2048*Cn],  g_qwl[(size_t)2048*Cn];
__device__ __nv_bfloat16 g_vwh[(size_t)4096*Cn],  g_vwl[(size_t)4096*Cn];
__device__ __nv_bfloat16 g_owh[(size_t)2048*Cn],  g_owl[(size_t)2048*Cn];
__device__ __nv_bfloat16 g_obh[(size_t)Mtok*VALD], g_obl[(size_t)Mtok*VALD];

// -------------------- cp.async helpers --------------------
__device__ __forceinline__ void cp16(void* s, const void* g) {
    unsigned ss = (unsigned)__cvta_generic_to_shared(s);
    asm volatile("cp.async.cg.shared.global [%0], [%1], 16;\n" :: "r"(ss), "l"(g));
}
__device__ __forceinline__ void cp16s(unsigned saddr, const void* g) {
    asm volatile("cp.async.cg.shared.global [%0], [%1], 16;\n" :: "r"(saddr), "l"(g));
}
__device__ __forceinline__ void cp4(void* s, const void* g) {
    unsigned ss = (unsigned)__cvta_generic_to_shared(s);
    asm volatile("cp.async.ca.shared.global [%0], [%1], 4;\n" :: "r"(ss), "l"(g));
}
#define CP_COMMIT asm volatile("cp.async.commit_group;\n" ::: "memory")
#define CP_WAIT1  asm volatile("cp.async.wait_group 1;\n" ::: "memory")
#define CP_WAIT0  asm volatile("cp.async.wait_group 0;\n" ::: "memory")

// bf16 mma m16n8k16: 1024 FLOP/instr
__device__ __forceinline__ void mma16(float* c, const unsigned* a, const unsigned* b) {
    asm volatile(
        "mma.sync.aligned.m16n8k16.row.col.f32.bf16.bf16.f32 "
        "{%0,%1,%2,%3},{%4,%5,%6,%7},{%8,%9},{%0,%1,%2,%3};\n"
        : "+f"(c[0]), "+f"(c[1]), "+f"(c[2]), "+f"(c[3])
        : "r"(a[0]), "r"(a[1]), "r"(a[2]), "r"(a[3]), "r"(b[0]), "r"(b[1]));
}

// ==================== bf16 hi/lo split ====================
__global__ __launch_bounds__(256) void split_bf16(
    const float* __restrict__ in, __nv_bfloat16* __restrict__ h,
    __nv_bfloat16* __restrict__ l, int n4)
{
    int i = blockIdx.x * blockDim.x + threadIdx.x;
    if (i >= n4) return;
    float4 v = ((const float4*)in)[i];
    __nv_bfloat162 h0, h1, l0, l1;
    h0.x = __float2bfloat16(v.x); l0.x = __float2bfloat16(v.x - __bfloat162float(h0.x));
    h0.y = __float2bfloat16(v.y); l0.y = __float2bfloat16(v.y - __bfloat162float(h0.y));
    h1.x = __float2bfloat16(v.z); l1.x = __float2bfloat16(v.z - __bfloat162float(h1.x));
    h1.y = __float2bfloat16(v.w); l1.y = __float2bfloat16(v.w - __bfloat162float(h1.y));
    ((__nv_bfloat162*)h)[2*i]   = h0; ((__nv_bfloat162*)h)[2*i+1] = h1;
    ((__nv_bfloat162*)l)[2*i]   = l0; ((__nv_bfloat162*)l)[2*i+1] = l1;
}

// ==================== bf16x3 GEMM: C[M,N] = A @ B^T ====================
// A = Ah+Al [M,K] bf16 pairs, B = Bh+Bl [N,K]. C fp32.
// C += Al*Bh + Ah*Bl + Ah*Bh  (lo*lo dropped; error ~2^-16)
// 256 threads, tile 128x128, K-chunk 32.
#define GBM 128
#define GBN 128
#define GBK 32
#define RST 40                         // row stride in bf16 elems (80B) - bank-conflict-free
#define BUFB (128*RST*2)               // 10240 B per operand buffer
#define STGB (4*BUFB)                  // Ah,Al,Bh,Bl per stage = 40960 B
#define GEMM_SMEM (2*STGB)             // 81920 B

__global__ __launch_bounds__(256) void gemm_bf16x3(
    const __nv_bfloat16* __restrict__ Ah, const __nv_bfloat16* __restrict__ Al,
    const __nv_bfloat16* __restrict__ Bh, const __nv_bfloat16* __restrict__ Bl,
    float* __restrict__ C, int M, int N, int K)
{
    extern __shared__ __align__(16) char dyn[];
    const unsigned sbase = (unsigned)__cvta_generic_to_shared(dyn);

    const int bm = blockIdx.y * GBM, bn = blockIdx.x * GBN;
    const int tid = threadIdx.x, lane = tid & 31, wid = tid >> 5;
    const int wm = (wid >> 2) * 64, wn = (wid & 3) * 32;
    const int g4 = lane >> 2, t4 = lane & 3;

    float acc[4][4][4];
#pragma unroll
    for (int i = 0; i < 4; i++)
#pragma unroll
        for (int j = 0; j < 4; j++)
#pragma unroll
            for (int r = 0; r < 4; r++) acc[i][j][r] = 0.f;

    const int nk = K / GBK;

    // per-stage buffers: [Ah | Al | Bh | Bl], each 128 rows x 32 bf16 (stride RST)
#define LOADSTAGE(s, k0) {                                                        \
        unsigned sb = sbase + (s) * STGB;                                         \
        _Pragma("unroll")                                                         \
        for (int rr = 0; rr < 2; rr++) {                                          \
            int idx = tid + rr * 256;                                             \
            int row = idx >> 2, cb = (idx & 3) * 8;   /* elem col */              \
            unsigned so = (unsigned)(row * (RST*2) + cb * 2);                     \
            size_t ga = (size_t)(bm + row) * K + (k0) + cb;                       \
            size_t gb = (size_t)(bn + row) * K + (k0) + cb;                       \
            cp16s(sb            + so, Ah + ga);                                   \
            cp16s(sb +   BUFB   + so, Al + ga);                                   \
            cp16s(sb + 2*BUFB   + so, Bh + gb);                                   \
            cp16s(sb + 3*BUFB   + so, Bl + gb);                                   \
        }                                                                         \
    }

    LOADSTAGE(0, 0);
    CP_COMMIT;

    const __nv_bfloat16* AhS = (const __nv_bfloat16*)dyn;

    for (int kt = 0; kt < nk; kt++) {
        const int s = kt & 1;
        if (kt + 1 < nk) LOADSTAGE(s ^ 1, (kt + 1) * GBK);
        CP_COMMIT;
        CP_WAIT1;
        __syncthreads();

        const unsigned* uAh = (const unsigned*)(AhS + (size_t)s * STGB / 2);
        const unsigned* uAl = uAh + BUFB / 4;
        const unsigned* uBh = uAh + 2 * (BUFB / 4);
        const unsigned* uBl = uAh + 3 * (BUFB / 4);
        // word-stride per row = RST/2 = 20
#pragma unroll
        for (int ks = 0; ks < 2; ks++) {
            const int kk = ks * 16;                // k offset (elems)
            const int kw = kk >> 1;                // word offset
            unsigned ah[4][4], al[4][4], bh[4][2], bl[4][2];
#pragma unroll
            for (int mf = 0; mf < 4; mf++) {
                int r0 = (wm + mf * 16 + g4) * 20 + kw + t4;
                int r8 = r0 + 8 * 20;
                ah[mf][0] = uAh[r0];     ah[mf][1] = uAh[r8];
                ah[mf][2] = uAh[r0 + 4]; ah[mf][3] = uAh[r8 + 4];
                al[mf][0] = uAl[r0];     al[mf][1] = uAl[r8];
                al[mf][2] = uAl[r0 + 4]; al[mf][3] = uAl[r8 + 4];
            }
#pragma unroll
            for (int nf = 0; nf < 4; nf++) {
                int c0 = (wn + nf * 8 + g4) * 20 + kw + t4;
                bh[nf][0] = uBh[c0]; bh[nf][1] = uBh[c0 + 4];
                bl[nf][0] = uBl[c0]; bl[nf][1] = uBl[c0 + 4];
            }
#pragma unroll
            for (int mf = 0; mf < 4; mf++)
#pragma unroll
                for (int nf = 0; nf < 4; nf++) {
                    mma16(acc[mf][nf], al[mf], bh[nf]);   // lo*hi
                    mma16(acc[mf][nf], ah[mf], bl[nf]);   // hi*lo
                    mma16(acc[mf][nf], ah[mf], bh[nf]);   // hi*hi
                }
        }
        __syncthreads();
    }

    // epilogue
#pragma unroll
    for (int mf = 0; mf < 4; mf++) {
#pragma unroll
        for (int nf = 0; nf < 4; nf++) {
            int row = bm + wm + mf * 16 + g4;
            int col = bn + wn + nf * 8 + 2 * t4;
            float2 v0 = make_float2(acc[mf][nf][0], acc[mf][nf][1]);
            float2 v1 = make_float2(acc[mf][nf][2], acc[mf][nf][3]);
            *(float2*)(C + (size_t)row * N + col)       = v0;
            *(float2*)(C + (size_t)(row + 8) * N + col) = v1;
        }
    }
#undef LOADSTAGE
}

// ==================== beta / decay projections ====================
__global__ __launch_bounds__(256) void proj_gb(
    const float* __restrict__ x,
    const float* __restrict__ aw, const float* __restrict__ bw,
    const float* __restrict__ bbias, const float* __restrict__ betab,
    const float* __restrict__ alog, const float* __restrict__ dtb,
    float* __restrict__ decout, float* __restrict__ betaout)
{
    const int m = blockIdx.x;
    const int tid = threadIdx.x, lane = tid & 31, wid = tid >> 5;
    __shared__ float raw[32];
    const float* xr = x + (size_t)m * Cn;
#pragma unroll
    for (int i = 0; i < 4; i++) {
        int idx = wid * 4 + i;
        const float* wr = (idx < 16) ? (aw + (size_t)idx * Cn)
                                     : (bw + (size_t)(idx - 16) * Cn);
        float accv = 0.f;
        for (int k2 = lane; k2 < Cn; k2 += 32) accv += xr[k2] * wr[k2];
#pragma unroll
        for (int o = 16; o; o >>= 1) accv += __shfl_xor_sync(0xffffffffu, accv, o);
        if (lane == 0) raw[idx] = accv;
    }
    __syncthreads();
    if (tid < 16) {
        int h = tid;
        float sa = raw[h] + dtb[h];
        float sp = (sa > 20.f) ? sa : log1pf(expf(sa));
        float g  = -expf(alog[h]) * sp;
        decout[(size_t)m * Hn + h] = expf(g);
        float sb = raw[16 + h] + bbias[h] + betab[h];
        betaout[(size_t)m * Hn + h] = 2.f / (1.f + expf(-sb));
    }
}

// ==================== causal depthwise conv(4) + silu ====================
__global__ void conv_silu(
    const float* __restrict__ in, int ldin, int off,
    const float* __restrict__ w, float* __restrict__ out,
    int CH, int total)
{
    int idx = blockIdx.x * blockDim.x + threadIdx.x;
    if (idx >= total) return;
    int c = idx % CH;
    int t = (idx / CH) % Tn;
    int b = idx / (CH * Tn);
    const float* w4 = w + (size_t)c * 4;
    size_t base = ((size_t)b * Tn) * ldin + off + c;
    float accv = 0.f;
#pragma unroll
    for (int j = 0; j < 4; j++) {
        int tt = t + j - 3;
        if (tt >= 0) accv += w4[j] * in[base + (size_t)tt * ldin];
    }
    out[idx] = accv / (1.f + expf(-accv));
}

// ==================== l2 norm over DK=64 groups ====================
__global__ __launch_bounds__(256) void l2norm_scale(
    float* __restrict__ p, int ngroups, float scale)
{
    int grp = blockIdx.x * 8 + (threadIdx.x >> 5);
    if (grp >= ngroups) return;
    int lane = threadIdx.x & 31;
    float* ptr = p + (size_t)grp * 64;
    float a = ptr[lane], b2 = ptr[lane + 32];
    float ss = a * a + b2 * b2;
#pragma unroll
    for (int o = 16; o; o >>= 1) ss += __shfl_xor_sync(0xffffffffu, ss, o);
    float r = rsqrtf(ss + 1e-6f) * scale;
    ptr[lane] = a * r;
    ptr[lane + 32] = b2 * r;
}

// ==================== gated delta rule recurrent scan ====================
#define SPLIT 2
#define CHK 16
__global__ __launch_bounds__(128) void scan_kernel(
    const float* __restrict__ qn, const float* __restrict__ kn,
    const float* __restrict__ vv, const float* __restrict__ dec,
    const float* __restrict__ bet, float* __restrict__ op)
{
    __shared__ __align__(16) float qs[2][CHK][64];
    __shared__ __align__(16) float ks[2][CHK][64];
    __shared__ __align__(16) float vs[2][CHK][64];
    __shared__ float gs[2][CHK], bs[2][CHK];

    const int bid = blockIdx.x;
    const int vh = bid & (SPLIT - 1);
    const int h  = (bid / SPLIT) & (Hn - 1);
    const int b  = bid / (SPLIT * Hn);
    const int tid = threadIdx.x;
    const int jl = tid >> 1, kh = tid & 1;

    float S[32];
#pragma unroll
    for (int i = 0; i < 32; i++) S[i] = 0.f;

#define LOADCHUNK(s, t0) {                                                          \
        _Pragma("unroll")                                                           \
        for (int rr = 0; rr < 2; rr++) {                                            \
            int idx = tid + rr * 128;                                               \
            int row = idx >> 4, q4i = (idx & 15) * 4;                               \
            size_t tb = (size_t)(b * Tn + (t0) + row);                              \
            cp16(&qs[s][row][q4i], qn + (tb * Hn + h) * 64 + q4i);                  \
            cp16(&ks[s][row][q4i], kn + (tb * Hn + h) * 64 + q4i);                  \
            cp16(&vs[s][row][q4i], vv + tb * VALD + h * DVn + vh * 64 + q4i);       \
        }                                                                           \
        if (tid < CHK)            cp4(&gs[s][tid],      dec + (size_t)(b*Tn+(t0)+tid)*Hn + h);        \
        else if (tid < 2*CHK)     cp4(&bs[s][tid-CHK],  bet + (size_t)(b*Tn+(t0)+tid-CHK)*Hn + h);    \
    }

    LOADCHUNK(0, 0);
    CP_COMMIT;

    const int NC = Tn / CHK;
    for (int c = 0; c < NC; c++) {
        const int s = c & 1;
        if (c + 1 < NC) LOADCHUNK(s ^ 1, (c + 1) * CHK);
        CP_COMMIT;
        CP_WAIT1;
        __syncthreads();

        const int t0 = c * CHK;
#pragma unroll 1
        for (int r = 0; r < CHK; r++) {
            const float ge  = gs[s][r];
            const float btc = bs[s][r];
            const float vj  = vs[s][r][jl];
            const float4* kp = (const float4*)&ks[s][r][kh * 32];
            const float4* qp = (const float4*)&qs[s][r][kh * 32];

            float kreg[32];
            float m0 = 0.f, m1 = 0.f, m2 = 0.f, m3 = 0.f;
#pragma unroll
            for (int i = 0; i < 8; i++) {
                float4 k4 = kp[i];
                float s0 = S[4*i+0] * ge, s1 = S[4*i+1] * ge;
                float s2 = S[4*i+2] * ge, s3 = S[4*i+3] * ge;
                m0 += k4.x * s0; m1 += k4.y * s1; m2 += k4.z * s2; m3 += k4.w * s3;
                S[4*i+0] = s0; S[4*i+1] = s1; S[4*i+2] = s2; S[4*i+3] = s3;
                kreg[4*i+0] = k4.x; kreg[4*i+1] = k4.y;
                kreg[4*i+2] = k4.z; kreg[4*i+3] = k4.w;
            }
            float mem = (m0 + m1) + (m2 + m3);
            mem += __shfl_xor_sync(0xffffffffu, mem, 1);
            const float delta = (vj - mem) * btc;

            float o0 = 0.f, o1 = 0.f, o2 = 0.f, o3 = 0.f;
#pragma unroll
            for (int i = 0; i < 8; i++) {
                float4 q4 = qp[i];
                float s0 = S[4*i+0] + kreg[4*i+0] * delta;
                float s1 = S[4*i+1] + kreg[4*i+1] * delta;
                float s2 = S[4*i+2] + kreg[4*i+2] * delta;
                float s3 = S[4*i+3] + kreg[4*i+3] * delta;
                o0 += q4.x * s0; o1 += q4.y * s1; o2 += q4.z * s2; o3 += q4.w * s3;
                S[4*i+0] = s0; S[4*i+1] = s1; S[4*i+2] = s2; S[4*i+3] = s3;
            }
            float ov = (o0 + o1) + (o2 + o3);
            ov += __shfl_xor_sync(0xffffffffu, ov, 1);
            if (kh == 0)
                op[(((size_t)(b * Tn + t0 + r)) * Hn + h) * DVn + vh * 64 + jl] = ov;
        }
        __syncthreads();
    }
#undef LOADCHUNK
}

// ==================== RMS over DV + silu(g_out) gate ====================
__global__ __launch_bounds__(256) void rms_gate(
    const float* __restrict__ op, const float* __restrict__ vg,
    float* __restrict__ ob)
{
    int grp = blockIdx.x * 8 + (threadIdx.x >> 5);   // grp = m*16 + h
    int lane = threadIdx.x & 31;
    const float4* src = (const float4*)(op + (size_t)grp * 128);
    float4 o4 = src[lane];
    float ss = o4.x * o4.x + o4.y * o4.y + o4.z * o4.z + o4.w * o4.w;
#pragma unroll
    for (int o = 16; o; o >>= 1) ss += __shfl_xor_sync(0xffffffffu, ss, o);
    float r = rsqrtf(ss * (1.f / 128.f) + 1.1920929e-7f);
    int m = grp >> 4, h = grp & 15;
    const float4* gp = (const float4*)(vg + (size_t)m * 4096 + 2048 + h * 128);
    float4 gg = gp[lane];
    float4 res;
    res.x = o4.x * r * (gg.x / (1.f + expf(-gg.x)));
    res.y = o4.y * r * (gg.y / (1.f + expf(-gg.y)));
    res.z = o4.z * r * (gg.z / (1.f + expf(-gg.z)));
    res.w = o4.w * r * (gg.w / (1.f + expf(-gg.w)));
    ((float4*)(ob + (size_t)m * 2048 + h * 128))[lane] = res;
}

// ==================== launch ====================
extern "C" void kernel_launch(void* const* d_in, const int* in_sizes, int n_in,
                              void* d_out, int out_size)
{
    const float* x      = (const float*)d_in[0];
    const float* qk_w   = (const float*)d_in[1];
    const float* vg_w   = (const float*)d_in[2];
    const float* o_w    = (const float*)d_in[3];
    const float* a_w    = (const float*)d_in[4];
    const float* b_w    = (const float*)d_in[5];
    const float* b_bias = (const float*)d_in[6];
    const float* beta_b = (const float*)d_in[7];
    const float* A_log  = (const float*)d_in[8];
    const float* dt_b   = (const float*)d_in[9];
    const float* q_cw   = (const float*)d_in[10];
    const float* k_cw   = (const float*)d_in[11];
    const float* v_cw   = (const float*)d_in[12];
    float* out = (float*)d_out;

    float *qk, *vg, *q, *k, *v, *dc, *bt, *op, *ob;
    __nv_bfloat16 *xh, *xl, *qwh, *qwl, *vwh, *vwl, *owh, *owl, *obh, *obl;
    cudaGetSymbolAddress((void**)&qk, g_qk);
    cudaGetSymbolAddress((void**)&vg, g_vg);
    cudaGetSymbolAddress((void**)&q,  g_q);
    cudaGetSymbolAddress((void**)&k,  g_k);
    cudaGetSymbolAddress((void**)&v,  g_v);
    cudaGetSymbolAddress((void**)&dc, g_dc);
    cudaGetSymbolAddress((void**)&bt, g_bt);
    cudaGetSymbolAddress((void**)&op, g_op);
    cudaGetSymbolAddress((void**)&ob, g_ob);
    cudaGetSymbolAddress((void**)&xh, g_xh);   cudaGetSymbolAddress((void**)&xl, g_xl);
    cudaGetSymbolAddress((void**)&qwh, g_qwh); cudaGetSymbolAddress((void**)&qwl, g_qwl);
    cudaGetSymbolAddress((void**)&vwh, g_vwh); cudaGetSymbolAddress((void**)&vwl, g_vwl);
    cudaGetSymbolAddress((void**)&owh, g_owh); cudaGetSymbolAddress((void**)&owl, g_owl);
    cudaGetSymbolAddress((void**)&obh, g_obh); cudaGetSymbolAddress((void**)&obl, g_obl);

    cudaFuncSetAttribute(gemm_bf16x3, cudaFuncAttributeMaxDynamicSharedMemorySize, GEMM_SMEM);

    // 0) bf16 hi/lo splits
    split_bf16<<<(Mtok*Cn/4 + 255)/256, 256>>>(x, xh, xl, Mtok*Cn/4);
    split_bf16<<<(2048*Cn/4 + 255)/256, 256>>>(qk_w, qwh, qwl, 2048*Cn/4);
    split_bf16<<<(4096*Cn/4 + 255)/256, 256>>>(vg_w, vwh, vwl, 4096*Cn/4);
    split_bf16<<<(2048*Cn/4 + 255)/256, 256>>>(o_w,  owh, owl, 2048*Cn/4);

    // 1) big projections (bf16x3 split precision on tensor pipe)
    gemm_bf16x3<<<dim3(2048/GBN, Mtok/GBM), 256, GEMM_SMEM>>>(xh, xl, qwh, qwl, qk, Mtok, 2048, Cn);
    gemm_bf16x3<<<dim3(4096/GBN, Mtok/GBM), 256, GEMM_SMEM>>>(xh, xl, vwh, vwl, vg, Mtok, 4096, Cn);

    // 2) beta + decay
    proj_gb<<<Mtok, 256>>>(x, a_w, b_w, b_bias, beta_b, A_log, dt_b, dc, bt);

    // 3) depthwise conv + silu
    {
        int tq = Mtok * KEYD;
        conv_silu<<<(tq + 255) / 256, 256>>>(qk, 2048, 0,    q_cw, q, KEYD, tq);
        conv_silu<<<(tq + 255) / 256, 256>>>(qk, 2048, KEYD, k_cw, k, KEYD, tq);
        int tv = Mtok * VALD;
        conv_silu<<<(tv + 255) / 256, 256>>>(vg, 4096, 0,    v_cw, v, VALD, tv);
    }

    // 4) l2 norm
    l2norm_scale<<<Mtok * Hn / 8, 256>>>(q, Mtok * Hn, 0.125f);
    l2norm_scale<<<Mtok * Hn / 8, 256>>>(k, Mtok * Hn, 1.0f);

    // 5) recurrent scan
    scan_kernel<<<Bsz * Hn * SPLIT, 128>>>(q, k, v, dc, bt, op);

    // 6) RMS + gate
    rms_gate<<<Mtok * Hn / 8, 256>>>(op, vg, ob);

    // 7) output projection
    split_bf16<<<(Mtok*VALD/4 + 255)/256, 256>>>(ob, obh, obl, Mtok*VALD/4);
    gemm_bf16x3<<<dim3(2048/GBN, Mtok/GBM), 256, GEMM_SMEM>>>(obh, obl, owh, owl, out, Mtok, 2048, Cn);
}

// round 5
// speedup vs baseline: 1.8335x; 1.1368x over previous
#include <cuda_runtime.h>
#include <cuda_bf16.h>
#include <math.h>
#include <stdint.h>

// Problem constants
#define Bsz 4
#define Tn 2048
#define Cn 2048
#define Hn 16
#define DKn 64
#define DVn 128
#define Mtok (Bsz*Tn)          // 8192
#define KEYD (Hn*DKn)          // 1024
#define VALD (Hn*DVn)          // 2048

// -------------------- scratch (device globals, no allocation) --------------------
__device__ float g_qk[(size_t)Mtok*2048];   // x @ qk_w^T
__device__ float g_vg[(size_t)Mtok*4096];   // x @ vg_w^T
__device__ float g_q [(size_t)Mtok*KEYD];
__device__ float g_k [(size_t)Mtok*KEYD];
__device__ float g_v [(size_t)Mtok*VALD];
__device__ float g_dc[(size_t)Mtok*Hn];
__device__ float g_bt[(size_t)Mtok*Hn];
__device__ float g_op[(size_t)Mtok*VALD];

// bf16 hi/lo split operands for the tensor GEMMs
__device__ __nv_bfloat16 g_xh [(size_t)Mtok*Cn],  g_xl [(size_t)Mtok*Cn];
__device__ __nv_bfloat16 g_qwh[(size_t)2048*Cn],  g_qwl[(size_t)2048*Cn];
__device__ __nv_bfloat16 g_vwh[(size_t)4096*Cn],  g_vwl[(size_t)4096*Cn];
__device__ __nv_bfloat16 g_owh[(size_t)2048*Cn],  g_owl[(size_t)2048*Cn];
__device__ __nv_bfloat16 g_obh[(size_t)Mtok*VALD], g_obl[(size_t)Mtok*VALD];

// -------------------- cp.async helpers --------------------
__device__ __forceinline__ void cp16(void* s, const void* g) {
    unsigned ss = (unsigned)__cvta_generic_to_shared(s);
    asm volatile("cp.async.cg.shared.global [%0], [%1], 16;\n" :: "r"(ss), "l"(g));
}
__device__ __forceinline__ void cp16s(unsigned saddr, const void* g) {
    asm volatile("cp.async.cg.shared.global [%0], [%1], 16;\n" :: "r"(saddr), "l"(g));
}
__device__ __forceinline__ void cp4(void* s, const void* g) {
    unsigned ss = (unsigned)__cvta_generic_to_shared(s);
    asm volatile("cp.async.ca.shared.global [%0], [%1], 4;\n" :: "r"(ss), "l"(g));
}
#define CP_COMMIT asm volatile("cp.async.commit_group;\n" ::: "memory")
#define CP_WAIT1  asm volatile("cp.async.wait_group 1;\n" ::: "memory")
#define CP_WAIT0  asm volatile("cp.async.wait_group 0;\n" ::: "memory")

// bf16 mma m16n8k16
__device__ __forceinline__ void mma16(float* c, const unsigned* a, const unsigned* b) {
    asm volatile(
        "mma.sync.aligned.m16n8k16.row.col.f32.bf16.bf16.f32 "
        "{%0,%1,%2,%3},{%4,%5,%6,%7},{%8,%9},{%0,%1,%2,%3};\n"
        : "+f"(c[0]), "+f"(c[1]), "+f"(c[2]), "+f"(c[3])
        : "r"(a[0]), "r"(a[1]), "r"(a[2]), "r"(a[3]), "r"(b[0]), "r"(b[1]));
}

__device__ __forceinline__ void ldm_x4(unsigned& r0, unsigned& r1,
                                       unsigned& r2, unsigned& r3, unsigned addr) {
    asm volatile("ldmatrix.sync.aligned.m8n8.x4.shared.b16 {%0,%1,%2,%3}, [%4];"
                 : "=r"(r0), "=r"(r1), "=r"(r2), "=r"(r3) : "r"(addr));
}

// ==================== bf16 hi/lo split ====================
__global__ __launch_bounds__(256) void split_bf16(
    const float* __restrict__ in, __nv_bfloat16* __restrict__ h,
    __nv_bfloat16* __restrict__ l, int n4)
{
    int i = blockIdx.x * blockDim.x + threadIdx.x;
    if (i >= n4) return;
    float4 v = ((const float4*)in)[i];
    __nv_bfloat162 h0, h1, l0, l1;
    h0.x = __float2bfloat16(v.x); l0.x = __float2bfloat16(v.x - __bfloat162float(h0.x));
    h0.y = __float2bfloat16(v.y); l0.y = __float2bfloat16(v.y - __bfloat162float(h0.y));
    h1.x = __float2bfloat16(v.z); l1.x = __float2bfloat16(v.z - __bfloat162float(h1.x));
    h1.y = __float2bfloat16(v.w); l1.y = __float2bfloat16(v.w - __bfloat162float(h1.y));
    ((__nv_bfloat162*)h)[2*i]   = h0; ((__nv_bfloat162*)h)[2*i+1] = h1;
    ((__nv_bfloat162*)l)[2*i]   = l0; ((__nv_bfloat162*)l)[2*i+1] = l1;
}

// ==================== bf16x3 GEMM with ldmatrix: C[M,N] = A @ B^T ====================
#define GBM 128
#define GBN 128
#define GBK 32
#define RST 40                         // row stride in bf16 elems (80B)
#define BUFB (128*RST*2)               // 10240 B per operand buffer
#define STGB (4*BUFB)                  // Ah,Al,Bh,Bl per stage = 40960 B
#define GEMM_SMEM (2*STGB)             // 81920 B

__global__ __launch_bounds__(256) void gemm_bf16x3(
    const __nv_bfloat16* __restrict__ Ah, const __nv_bfloat16* __restrict__ Al,
    const __nv_bfloat16* __restrict__ Bh, const __nv_bfloat16* __restrict__ Bl,
    float* __restrict__ C, int M, int N, int K)
{
    extern __shared__ __align__(16) char dyn[];
    const unsigned sbase = (unsigned)__cvta_generic_to_shared(dyn);

    const int bm = blockIdx.y * GBM, bn = blockIdx.x * GBN;
    const int tid = threadIdx.x, lane = tid & 31, wid = tid >> 5;
    const int wm = (wid >> 2) * 64, wn = (wid & 3) * 32;
    const int g4 = lane >> 2, t4 = lane & 3;

    // ldmatrix per-lane address components
    const int r8 = lane & 7, sel = lane >> 3;
    unsigned aoff[4], boff[2];
#pragma unroll
    for (int mf = 0; mf < 4; mf++)
        aoff[mf] = (unsigned)((wm + mf * 16 + r8 + ((sel & 1) << 3)) * (RST*2)
                              + ((sel >> 1) << 4));
#pragma unroll
    for (int p = 0; p < 2; p++)
        boff[p] = (unsigned)((wn + p * 16 + r8 + ((sel >> 1) << 3)) * (RST*2)
                              + ((sel & 1) << 4));

    float acc[4][4][4];
#pragma unroll
    for (int i = 0; i < 4; i++)
#pragma unroll
        for (int j = 0; j < 4; j++)
#pragma unroll
            for (int r = 0; r < 4; r++) acc[i][j][r] = 0.f;

    const int nk = K / GBK;

#define LOADSTAGE(s, k0) {                                                        \
        unsigned sb = sbase + (s) * STGB;                                         \
        _Pragma("unroll")                                                         \
        for (int rr = 0; rr < 2; rr++) {                                          \
            int idx = tid + rr * 256;                                             \
            int row = idx >> 2, cb = (idx & 3) * 8;                               \
            unsigned so = (unsigned)(row * (RST*2) + cb * 2);                     \
            size_t ga = (size_t)(bm + row) * K + (k0) + cb;                       \
            size_t gb = (size_t)(bn + row) * K + (k0) + cb;                       \
            cp16s(sb            + so, Ah + ga);                                   \
            cp16s(sb +   BUFB   + so, Al + ga);                                   \
            cp16s(sb + 2*BUFB   + so, Bh + gb);                                   \
            cp16s(sb + 3*BUFB   + so, Bl + gb);                                   \
        }                                                                         \
    }

    LOADSTAGE(0, 0);
    CP_COMMIT;

    for (int kt = 0; kt < nk; kt++) {
        const int s = kt & 1;
        if (kt + 1 < nk) LOADSTAGE(s ^ 1, (kt + 1) * GBK);
        CP_COMMIT;
        CP_WAIT1;
        __syncthreads();

        const unsigned abase = sbase + s * STGB;
#pragma unroll
        for (int ks = 0; ks < 2; ks++) {
            const unsigned kb = (unsigned)(ks * 32);   // bytes (16 elems)
            unsigned ah[4][4], al[4][4], bh[4][2], bl[4][2];
#pragma unroll
            for (int mf = 0; mf < 4; mf++) {
                unsigned ad = abase + aoff[mf] + kb;
                ldm_x4(ah[mf][0], ah[mf][1], ah[mf][2], ah[mf][3], ad);
                ldm_x4(al[mf][0], al[mf][1], al[mf][2], al[mf][3], ad + BUFB);
            }
#pragma unroll
            for (int p = 0; p < 2; p++) {
                unsigned bd = abase + 2*BUFB + boff[p] + kb;
                ldm_x4(bh[2*p][0], bh[2*p][1], bh[2*p+1][0], bh[2*p+1][1], bd);
                ldm_x4(bl[2*p][0], bl[2*p][1], bl[2*p+1][0], bl[2*p+1][1], bd + BUFB);
            }
#pragma unroll
            for (int mf = 0; mf < 4; mf++)
#pragma unroll
                for (int nf = 0; nf < 4; nf++) {
                    mma16(acc[mf][nf], al[mf], bh[nf]);   // lo*hi
                    mma16(acc[mf][nf], ah[mf], bl[nf]);   // hi*lo
                    mma16(acc[mf][nf], ah[mf], bh[nf]);   // hi*hi
                }
        }
        __syncthreads();
    }

    // epilogue
#pragma unroll
    for (int mf = 0; mf < 4; mf++) {
#pragma unroll
        for (int nf = 0; nf < 4; nf++) {
            int row = bm + wm + mf * 16 + g4;
            int col = bn + wn + nf * 8 + 2 * t4;
            float2 v0 = make_float2(acc[mf][nf][0], acc[mf][nf][1]);
            float2 v1 = make_float2(acc[mf][nf][2], acc[mf][nf][3]);
            *(float2*)(C + (size_t)row * N + col)       = v0;
            *(float2*)(C + (size_t)(row + 8) * N + col) = v1;
        }
    }
#undef LOADSTAGE
}

// ==================== beta / decay projections ====================
__global__ __launch_bounds__(256) void proj_gb(
    const float* __restrict__ x,
    const float* __restrict__ aw, const float* __restrict__ bw,
    const float* __restrict__ bbias, const float* __restrict__ betab,
    const float* __restrict__ alog, const float* __restrict__ dtb,
    float* __restrict__ decout, float* __restrict__ betaout)
{
    const int m = blockIdx.x;
    const int tid = threadIdx.x, lane = tid & 31, wid = tid >> 5;
    __shared__ float raw[32];
    const float* xr = x + (size_t)m * Cn;
#pragma unroll
    for (int i = 0; i < 4; i++) {
        int idx = wid * 4 + i;
        const float* wr = (idx < 16) ? (aw + (size_t)idx * Cn)
                                     : (bw + (size_t)(idx - 16) * Cn);
        float accv = 0.f;
        for (int k2 = lane; k2 < Cn; k2 += 32) accv += xr[k2] * wr[k2];
#pragma unroll
        for (int o = 16; o; o >>= 1) accv += __shfl_xor_sync(0xffffffffu, accv, o);
        if (lane == 0) raw[idx] = accv;
    }
    __syncthreads();
    if (tid < 16) {
        int h = tid;
        float sa = raw[h] + dtb[h];
        float sp = (sa > 20.f) ? sa : log1pf(expf(sa));
        float g  = -expf(alog[h]) * sp;
        decout[(size_t)m * Hn + h] = expf(g);
        float sb = raw[16 + h] + bbias[h] + betab[h];
        betaout[(size_t)m * Hn + h] = 2.f / (1.f + expf(-sb));
    }
}

// ==================== causal depthwise conv(4) + silu ====================
__global__ void conv_silu(
    const float* __restrict__ in, int ldin, int off,
    const float* __restrict__ w, float* __restrict__ out,
    int CH, int total)
{
    int idx = blockIdx.x * blockDim.x + threadIdx.x;
    if (idx >= total) return;
    int c = idx % CH;
    int t = (idx / CH) % Tn;
    int b = idx / (CH * Tn);
    const float* w4 = w + (size_t)c * 4;
    size_t base = ((size_t)b * Tn) * ldin + off + c;
    float accv = 0.f;
#pragma unroll
    for (int j = 0; j < 4; j++) {
        int tt = t + j - 3;
        if (tt >= 0) accv += w4[j] * in[base + (size_t)tt * ldin];
    }
    out[idx] = accv / (1.f + expf(-accv));
}

// ==================== l2 norm over DK=64 groups ====================
__global__ __launch_bounds__(256) void l2norm_scale(
    float* __restrict__ p, int ngroups, float scale)
{
    int grp = blockIdx.x * 8 + (threadIdx.x >> 5);
    if (grp >= ngroups) return;
    int lane = threadIdx.x & 31;
    float* ptr = p + (size_t)grp * 64;
    float a = ptr[lane], b2 = ptr[lane + 32];
    float ss = a * a + b2 * b2;
#pragma unroll
    for (int o = 16; o; o >>= 1) ss += __shfl_xor_sync(0xffffffffu, ss, o);
    float r = rsqrtf(ss + 1e-6f) * scale;
    ptr[lane] = a * r;
    ptr[lane + 32] = b2 * r;
}

// ==================== gated delta rule recurrent scan ====================
#define SPLIT 2
#define CHK 16
__global__ __launch_bounds__(128) void scan_kernel(
    const float* __restrict__ qn, const float* __restrict__ kn,
    const float* __restrict__ vv, const float* __restrict__ dec,
    const float* __restrict__ bet, float* __restrict__ op)
{
    __shared__ __align__(16) float qs[2][CHK][64];
    __shared__ __align__(16) float ks[2][CHK][64];
    __shared__ __align__(16) float vs[2][CHK][64];
    __shared__ float gs[2][CHK], bs[2][CHK];

    const int bid = blockIdx.x;
    const int vh = bid & (SPLIT - 1);
    const int h  = (bid / SPLIT) & (Hn - 1);
    const int b  = bid / (SPLIT * Hn);
    const int tid = threadIdx.x;
    const int jl = tid >> 1, kh = tid & 1;

    float S[32];
#pragma unroll
    for (int i = 0; i < 32; i++) S[i] = 0.f;

#define LOADCHUNK(s, t0) {                                                          \
        _Pragma("unroll")                                                           \
        for (int rr = 0; rr < 2; rr++) {                                            \
            int idx = tid + rr * 128;                                               \
            int row = idx >> 4, q4i = (idx & 15) * 4;                               \
            size_t tb = (size_t)(b * Tn + (t0) + row);                              \
            cp16(&qs[s][row][q4i], qn + (tb * Hn + h) * 64 + q4i);                  \
            cp16(&ks[s][row][q4i], kn + (tb * Hn + h) * 64 + q4i);                  \
            cp16(&vs[s][row][q4i], vv + tb * VALD + h * DVn + vh * 64 + q4i);       \
        }                                                                           \
        if (tid < CHK)            cp4(&gs[s][tid],      dec + (size_t)(b*Tn+(t0)+tid)*Hn + h);        \
        else if (tid < 2*CHK)     cp4(&bs[s][tid-CHK],  bet + (size_t)(b*Tn+(t0)+tid-CHK)*Hn + h);    \
    }

    LOADCHUNK(0, 0);
    CP_COMMIT;

    const int NC = Tn / CHK;
    for (int c = 0; c < NC; c++) {
        const int s = c & 1;
        if (c + 1 < NC) LOADCHUNK(s ^ 1, (c + 1) * CHK);
        CP_COMMIT;
        CP_WAIT1;
        __syncthreads();

        const int t0 = c * CHK;
#pragma unroll 1
        for (int r = 0; r < CHK; r++) {
            const float ge  = gs[s][r];
            const float btc = bs[s][r];
            const float vj  = vs[s][r][jl];
            const float4* kp = (const float4*)&ks[s][r][kh * 32];
            const float4* qp = (const float4*)&qs[s][r][kh * 32];

            float kreg[32];
            float m0 = 0.f, m1 = 0.f, m2 = 0.f, m3 = 0.f;
#pragma unroll
            for (int i = 0; i < 8; i++) {
                float4 k4 = kp[i];
                float s0 = S[4*i+0] * ge, s1 = S[4*i+1] * ge;
                float s2 = S[4*i+2] * ge, s3 = S[4*i+3] * ge;
                m0 += k4.x * s0; m1 += k4.y * s1; m2 += k4.z * s2; m3 += k4.w * s3;
                S[4*i+0] = s0; S[4*i+1] = s1; S[4*i+2] = s2; S[4*i+3] = s3;
                kreg[4*i+0] = k4.x; kreg[4*i+1] = k4.y;
                kreg[4*i+2] = k4.z; kreg[4*i+3] = k4.w;
            }
            float mem = (m0 + m1) + (m2 + m3);
            mem += __shfl_xor_sync(0xffffffffu, mem, 1);
            const float delta = (vj - mem) * btc;

            float o0 = 0.f, o1 = 0.f, o2 = 0.f, o3 = 0.f;
#pragma unroll
            for (int i = 0; i < 8; i++) {
                float4 q4 = qp[i];
                float s0 = S[4*i+0] + kreg[4*i+0] * delta;
                float s1 = S[4*i+1] + kreg[4*i+1] * delta;
                float s2 = S[4*i+2] + kreg[4*i+2] * delta;
                float s3 = S[4*i+3] + kreg[4*i+3] * delta;
                o0 += q4.x * s0; o1 += q4.y * s1; o2 += q4.z * s2; o3 += q4.w * s3;
                S[4*i+0] = s0; S[4*i+1] = s1; S[4*i+2] = s2; S[4*i+3] = s3;
            }
            float ov = (o0 + o1) + (o2 + o3);
            ov += __shfl_xor_sync(0xffffffffu, ov, 1);
            if (kh == 0)
                op[(((size_t)(b * Tn + t0 + r)) * Hn + h) * DVn + vh * 64 + jl] = ov;
        }
        __syncthreads();
    }
#undef LOADCHUNK
}

// ==================== RMS + silu gate, fused bf16 hi/lo split output ====================
__global__ __launch_bounds__(256) void rms_gate_split(
    const float* __restrict__ op, const float* __restrict__ vg,
    __nv_bfloat16* __restrict__ obh, __nv_bfloat16* __restrict__ obl)
{
    int grp = blockIdx.x * 8 + (threadIdx.x >> 5);   // grp = m*16 + h
    int lane = threadIdx.x & 31;
    const float4* src = (const float4*)(op + (size_t)grp * 128);
    float4 o4 = src[lane];
    float ss = o4.x * o4.x + o4.y * o4.y + o4.z * o4.z + o4.w * o4.w;
#pragma unroll
    for (int o = 16; o; o >>= 1) ss += __shfl_xor_sync(0xffffffffu, ss, o);
    float r = rsqrtf(ss * (1.f / 128.f) + 1.1920929e-7f);
    int m = grp >> 4, h = grp & 15;
    const float4* gp = (const float4*)(vg + (size_t)m * 4096 + 2048 + h * 128);
    float4 gg = gp[lane];
    float res[4];
    res[0] = o4.x * r * (gg.x / (1.f + expf(-gg.x)));
    res[1] = o4.y * r * (gg.y / (1.f + expf(-gg.y)));
    res[2] = o4.z * r * (gg.z / (1.f + expf(-gg.z)));
    res[3] = o4.w * r * (gg.w / (1.f + expf(-gg.w)));
    __nv_bfloat16 hv[4], lv[4];
#pragma unroll
    for (int i = 0; i < 4; i++) {
        hv[i] = __float2bfloat16(res[i]);
        lv[i] = __float2bfloat16(res[i] - __bfloat162float(hv[i]));
    }
    size_t off = (size_t)m * 2048 + h * 128 + lane * 4;
    *(uint2*)(obh + off) = *(uint2*)hv;
    *(uint2*)(obl + off) = *(uint2*)lv;
}

// ==================== launch ====================
extern "C" void kernel_launch(void* const* d_in, const int* in_sizes, int n_in,
                              void* d_out, int out_size)
{
    const float* x      = (const float*)d_in[0];
    const float* qk_w   = (const float*)d_in[1];
    const float* vg_w   = (const float*)d_in[2];
    const float* o_w    = (const float*)d_in[3];
    const float* a_w    = (const float*)d_in[4];
    const float* b_w    = (const float*)d_in[5];
    const float* b_bias = (const float*)d_in[6];
    const float* beta_b = (const float*)d_in[7];
    const float* A_log  = (const float*)d_in[8];
    const float* dt_b   = (const float*)d_in[9];
    const float* q_cw   = (const float*)d_in[10];
    const float* k_cw   = (const float*)d_in[11];
    const float* v_cw   = (const float*)d_in[12];
    float* out = (float*)d_out;

    float *qk, *vg, *q, *k, *v, *dc, *bt, *op;
    __nv_bfloat16 *xh, *xl, *qwh, *qwl, *vwh, *vwl, *owh, *owl, *obh, *obl;
    cudaGetSymbolAddress((void**)&qk, g_qk);
    cudaGetSymbolAddress((void**)&vg, g_vg);
    cudaGetSymbolAddress((void**)&q,  g_q);
    cudaGetSymbolAddress((void**)&k,  g_k);
    cudaGetSymbolAddress((void**)&v,  g_v);
    cudaGetSymbolAddress((void**)&dc, g_dc);
    cudaGetSymbolAddress((void**)&bt, g_bt);
    cudaGetSymbolAddress((void**)&op, g_op);
    cudaGetSymbolAddress((void**)&xh, g_xh);   cudaGetSymbolAddress((void**)&xl, g_xl);
    cudaGetSymbolAddress((void**)&qwh, g_qwh); cudaGetSymbolAddress((void**)&qwl, g_qwl);
    cudaGetSymbolAddress((void**)&vwh, g_vwh); cudaGetSymbolAddress((void**)&vwl, g_vwl);
    cudaGetSymbolAddress((void**)&owh, g_owh); cudaGetSymbolAddress((void**)&owl, g_owl);
    cudaGetSymbolAddress((void**)&obh, g_obh); cudaGetSymbolAddress((void**)&obl, g_obl);

    cudaFuncSetAttribute(gemm_bf16x3, cudaFuncAttributeMaxDynamicSharedMemorySize, GEMM_SMEM);

    // 0) bf16 hi/lo splits
    split_bf16<<<(Mtok*Cn/4 + 255)/256, 256>>>(x, xh, xl, Mtok*Cn/4);
    split_bf16<<<(2048*Cn/4 + 255)/256, 256>>>(qk_w, qwh, qwl, 2048*Cn/4);
    split_bf16<<<(4096*Cn/4 + 255)/256, 256>>>(vg_w, vwh, vwl, 4096*Cn/4);
    split_bf16<<<(2048*Cn/4 + 255)/256, 256>>>(o_w,  owh, owl, 2048*Cn/4);

    // 1) big projections (bf16x3 split precision, ldmatrix fragments)
    gemm_bf16x3<<<dim3(2048/GBN, Mtok/GBM), 256, GEMM_SMEM>>>(xh, xl, qwh, qwl, qk, Mtok, 2048, Cn);
    gemm_bf16x3<<<dim3(4096/GBN, Mtok/GBM), 256, GEMM_SMEM>>>(xh, xl, vwh, vwl, vg, Mtok, 4096, Cn);

    // 2) beta + decay
    proj_gb<<<Mtok, 256>>>(x, a_w, b_w, b_bias, beta_b, A_log, dt_b, dc, bt);

    // 3) depthwise conv + silu
    {
        int tq = Mtok * KEYD;
        conv_silu<<<(tq + 255) / 256, 256>>>(qk, 2048, 0,    q_cw, q, KEYD, tq);
        conv_silu<<<(tq + 255) / 256, 256>>>(qk, 2048, KEYD, k_cw, k, KEYD, tq);
        int tv = Mtok * VALD;
        conv_silu<<<(tv + 255) / 256, 256>>>(vg, 4096, 0,    v_cw, v, VALD, tv);
    }

    // 4) l2 norm
    l2norm_scale<<<Mtok * Hn / 8, 256>>>(q, Mtok * Hn, 0.125f);
    l2norm_scale<<<Mtok * Hn / 8, 256>>>(k, Mtok * Hn, 1.0f);

    // 5) recurrent scan
    scan_kernel<<<Bsz * Hn * SPLIT, 128>>>(q, k, v, dc, bt, op);

    // 6) RMS + gate + fused bf16 split
    rms_gate_split<<<Mtok * Hn / 8, 256>>>(op, vg, obh, obl);

    // 7) output projection
    gemm_bf16x3<<<dim3(2048/GBN, Mtok/GBM), 256, GEMM_SMEM>>>(obh, obl, owh, owl, out, Mtok, 2048, Cn);
}